// round 17
// baseline (speedup 1.0000x reference)
#include <cuda_runtime.h>
#include <cuda_bf16.h>

// ---------------- problem constants ----------------
#define BS    16
#define NTOK  3900
#define DIM   512
#define HEADS 8
#define DH    64
#define CTX   200
#define NB    20
#define MROWS (BS*NTOK)   // 62400

// ---------------- scratch ----------------
__device__ __nv_bfloat16 g_qkh[(size_t)MROWS * 1024];  // 128 MB bf16 [Q(scaled)|K]
__device__ float g_v  [(size_t)MROWS * DIM];           // 128 MB tf32 V
__device__ float g_ao [(size_t)MROWS * DIM];           // 128 MB attention out
__device__ unsigned g_wqkh[(DIM/2) * 1024];            // bf16-pair W[Qs|K] [kp][n]
__device__ unsigned g_th [399 * 32];                   // bf16-pair rel table rows 313..711

__device__ __forceinline__ unsigned f2tf(float f) {
    unsigned u; asm("cvt.rna.tf32.f32 %0, %1;" : "=r"(u) : "f"(f)); return u;
}
__device__ __forceinline__ float f2tf_f(float f) {
    return __uint_as_float(f2tf(f));
}
__device__ __forceinline__ unsigned pack_bf2(float lo, float hi) {
    __nv_bfloat162 p = __floats2bfloat162_rn(lo, hi);
    return *(unsigned*)&p;
}

// ---------------- packing kernels (only the two cheap irreducible ones) ------
// W[0.125*Wq | Wk] into bf16 k-pair layout: word(kp, n) = (W[2kp][n], W[2kp+1][n])
__global__ void pack_wqk(const float* __restrict__ wq, const float* __restrict__ wkv,
                         unsigned* __restrict__ w)
{
    int idx = blockIdx.x * 256 + threadIdx.x;
    if (idx >= (DIM/2) * 1024) return;
    int kp = idx >> 10, n = idx & 1023;
    float a, b;
    if (n < DIM) {
        a = 0.125f * wq[(2*kp) * DIM + n];
        b = 0.125f * wq[(2*kp+1) * DIM + n];
    } else {
        a = wkv[(2*kp) * 1024 + n-DIM];
        b = wkv[(2*kp+1) * 1024 + n-DIM];
    }
    w[idx] = pack_bf2(a, b);
}

__global__ void pack_t(const float* __restrict__ T, unsigned* __restrict__ th)
{
    int idx = blockIdx.x * 256 + threadIdx.x;
    if (idx >= 399 * 32) return;
    int r = idx >> 5, c2 = (idx & 31) * 2;
    float2 tv = *(const float2*)&T[(size_t)(313 + r) * DH + c2];
    th[idx] = pack_bf2(tv.x, tv.y);
}

__device__ __forceinline__ void mma_tf32(float* c, const unsigned* a,
                                         unsigned b0, unsigned b1)
{
    asm volatile(
        "mma.sync.aligned.m16n8k8.row.col.f32.tf32.tf32.f32 "
        "{%0,%1,%2,%3}, {%4,%5,%6,%7}, {%8,%9}, {%0,%1,%2,%3};\n"
        : "+f"(c[0]), "+f"(c[1]), "+f"(c[2]), "+f"(c[3])
        : "r"(a[0]), "r"(a[1]), "r"(a[2]), "r"(a[3]), "r"(b0), "r"(b1));
}

__device__ __forceinline__ void mma_bf16(float* c, const unsigned* a,
                                         unsigned b0, unsigned b1)
{
    asm volatile(
        "mma.sync.aligned.m16n8k16.row.col.f32.bf16.bf16.f32 "
        "{%0,%1,%2,%3}, {%4,%5,%6,%7}, {%8,%9}, {%0,%1,%2,%3};\n"
        : "+f"(c[0]), "+f"(c[1]), "+f"(c[2]), "+f"(c[3])
        : "r"(a[0]), "r"(a[1]), "r"(a[2]), "r"(a[3]), "r"(b0), "r"(b1));
}

__device__ __forceinline__ void cp16(unsigned dst, const void* src, bool pred) {
    int sz = pred ? 16 : 0;
    asm volatile("cp.async.cg.shared.global [%0], [%1], 16, %2;\n"
                 :: "r"(dst), "l"(src), "r"(sz));
}

// ---------------- pipelined tf32 GEMM (+ in-register A/B rounding, ldb) ------
#define BM 128
#define BN 128
#define BK2 32
#define ASTR3 36
#define BSTR 136
#define A_TILE_U32 (BM * ASTR3)          // 4608
#define B_TILE_U32 (BK2 * BSTR)          // 4352
#define GEMM_SMEM ((3 * (A_TILE_U32 + B_TILE_U32)) * 4)  // 107520 B

template<bool BIAS, bool CVTA, bool CVTB>
__global__ void __launch_bounds__(256, 2)
gemm_tf32(const float* __restrict__ A, const float* __restrict__ B,
          const float* __restrict__ bias, float* __restrict__ C,
          int M, int N, int K, int ldb, int ldc)
{
    extern __shared__ unsigned gsm[];
    unsigned* As = gsm;
    unsigned* Bs = gsm + 3 * A_TILE_U32;

    const int tid  = threadIdx.x;
    const int m0   = blockIdx.y * BM;
    const int n0   = blockIdx.x * BN;
    const int lane = tid & 31;
    const int wid  = tid >> 5;
    const int wm   = (wid & 1) * 64;
    const int wn   = (wid >> 1) * 32;
    const int lq   = lane & 3;
    const int lr   = lane >> 2;

    const unsigned aBase = (unsigned)__cvta_generic_to_shared(As);
    const unsigned bBase = (unsigned)__cvta_generic_to_shared(Bs);

    auto loadA = [&](int st, int k0) {
#pragma unroll
        for (int c = 0; c < 4; c++) {
            int chunk = c * 256 + tid;
            int row = chunk >> 3;
            int ch  = chunk & 7;
            bool v = (m0 + row) < M;
            cp16(aBase + (st * A_TILE_U32 + row * ASTR3 + ch * 4) * 4,
                 v ? &A[(size_t)(m0 + row) * K + k0 + ch * 4] : (const void*)A, v);
        }
    };
    auto loadB = [&](int st, int k0) {
#pragma unroll
        for (int c = 0; c < 4; c++) {
            int chunk = c * 256 + tid;
            int row = chunk >> 5;
            int ch  = chunk & 31;
            cp16(bBase + (st * B_TILE_U32 + row * BSTR + ch * 4) * 4,
                 &B[(size_t)(k0 + row) * ldb + n0 + ch * 4], true);
        }
    };

    float acc[4][4][4];
#pragma unroll
    for (int i = 0; i < 4; i++)
#pragma unroll
        for (int j = 0; j < 4; j++)
#pragma unroll
            for (int c = 0; c < 4; c++) acc[i][j][c] = 0.f;

    const int KT = K / BK2;

    loadA(0, 0); loadB(0, 0);
    asm volatile("cp.async.commit_group;\n");
    loadA(1, BK2); loadB(1, BK2);
    asm volatile("cp.async.commit_group;\n");

    int cur = 0, nxt = 2;
    for (int it = 0; it < KT; it++) {
        asm volatile("cp.async.wait_group %0;\n" :: "n"(1));
        __syncthreads();

        int pf = it + 2;
        if (pf < KT) { loadA(nxt, pf * BK2); loadB(nxt, pf * BK2); }
        asm volatile("cp.async.commit_group;\n");

        const unsigned* Ast = As + cur * A_TILE_U32;
        const unsigned* Bst = Bs + cur * B_TILE_U32;

#pragma unroll
        for (int ks = 0; ks < BK2; ks += 8) {
            unsigned af[4][4], bf[4][2];
#pragma unroll
            for (int tm = 0; tm < 4; tm++) {
                int m = wm + tm * 16 + lr;
                af[tm][0] = Ast[m * ASTR3 + ks + lq];
                af[tm][1] = Ast[(m + 8) * ASTR3 + ks + lq];
                af[tm][2] = Ast[m * ASTR3 + ks + lq + 4];
                af[tm][3] = Ast[(m + 8) * ASTR3 + ks + lq + 4];
                if (CVTA) {
                    af[tm][0] = f2tf(__uint_as_float(af[tm][0]));
                    af[tm][1] = f2tf(__uint_as_float(af[tm][1]));
                    af[tm][2] = f2tf(__uint_as_float(af[tm][2]));
                    af[tm][3] = f2tf(__uint_as_float(af[tm][3]));
                }
            }
#pragma unroll
            for (int tn = 0; tn < 4; tn++) {
                int n = wn + tn * 8 + lr;
                bf[tn][0] = Bst[(ks + lq) * BSTR + n];
                bf[tn][1] = Bst[(ks + lq + 4) * BSTR + n];
                if (CVTB) {
                    bf[tn][0] = f2tf(__uint_as_float(bf[tn][0]));
                    bf[tn][1] = f2tf(__uint_as_float(bf[tn][1]));
                }
            }
#pragma unroll
            for (int tm = 0; tm < 4; tm++)
#pragma unroll
                for (int tn = 0; tn < 4; tn++)
                    mma_tf32(acc[tm][tn], af[tm], bf[tn][0], bf[tn][1]);
        }
        cur = (cur == 2) ? 0 : cur + 1;
        nxt = (nxt == 2) ? 0 : nxt + 1;
    }

#pragma unroll
    for (int tm = 0; tm < 4; tm++) {
#pragma unroll
        for (int half = 0; half < 2; half++) {
            int row = m0 + wm + tm * 16 + lr + half * 8;
            if (row >= M) continue;
#pragma unroll
            for (int tn = 0; tn < 4; tn++) {
                int col = n0 + wn + tn * 8 + 2 * lq;
                float2 o;
                o.x = acc[tm][tn][half * 2 + 0];
                o.y = acc[tm][tn][half * 2 + 1];
                if (BIAS) { o.x += bias[col]; o.y += bias[col + 1]; }
                *(float2*)&C[(size_t)row * ldc + col] = o;
            }
        }
    }
}

// ---------------- pipelined bf16 GEMM: raw fp32 A, packed bf16 B, bf16 out ---
// A staged fp32 [BM][ASTR3]; fragments packed to bf16 in-register (LDS.64+cvt).
#define BH_TILE ((BK2/2) * BSTR)          // 2176
#define GEMMH_SMEM ((3 * (A_TILE_U32 + BH_TILE)) * 4)   // 81408 B

__global__ void __launch_bounds__(256, 2)
gemm_bf16(const float* __restrict__ A, const unsigned* __restrict__ B,
          __nv_bfloat16* __restrict__ C, int M, int N, int K, int ldc)
{
    extern __shared__ unsigned gsm[];
    unsigned* As = gsm;                      // [3][BM][ASTR3] fp32
    unsigned* Bs = gsm + 3 * A_TILE_U32;     // [3][BK2/2][BSTR] bf16-pair

    const int tid  = threadIdx.x;
    const int m0   = blockIdx.y * BM;
    const int n0   = blockIdx.x * BN;
    const int lane = tid & 31;
    const int wid  = tid >> 5;
    const int wm   = (wid & 1) * 64;
    const int wn   = (wid >> 1) * 32;
    const int lq   = lane & 3;
    const int lr   = lane >> 2;

    const unsigned aBase = (unsigned)__cvta_generic_to_shared(As);
    const unsigned bBase = (unsigned)__cvta_generic_to_shared(Bs);

    auto loadA = [&](int st, int k0) {
#pragma unroll
        for (int c = 0; c < 4; c++) {
            int chunk = c * 256 + tid;
            int row = chunk >> 3;
            int ch  = chunk & 7;
            bool v = (m0 + row) < M;
            cp16(aBase + (st * A_TILE_U32 + row * ASTR3 + ch * 4) * 4,
                 v ? &A[(size_t)(m0 + row) * K + k0 + ch * 4] : (const void*)A, v);
        }
    };
    auto loadB = [&](int st, int k0) {
        int kp0 = k0 >> 1;
#pragma unroll
        for (int c = 0; c < 2; c++) {
            int chunk = c * 256 + tid;
            int row = chunk >> 5;
            int ch  = chunk & 31;
            cp16(bBase + (st * BH_TILE + row * BSTR + ch * 4) * 4,
                 &B[(size_t)(kp0 + row) * N + n0 + ch * 4], true);
        }
    };

    float acc[4][4][4];
#pragma unroll
    for (int i = 0; i < 4; i++)
#pragma unroll
        for (int j = 0; j < 4; j++)
#pragma unroll
            for (int c = 0; c < 4; c++) acc[i][j][c] = 0.f;

    const int KT = K / BK2;

    loadA(0, 0); loadB(0, 0);
    asm volatile("cp.async.commit_group;\n");
    loadA(1, BK2); loadB(1, BK2);
    asm volatile("cp.async.commit_group;\n");

    int cur = 0, nxt = 2;
    for (int it = 0; it < KT; it++) {
        asm volatile("cp.async.wait_group %0;\n" :: "n"(1));
        __syncthreads();

        int pf = it + 2;
        if (pf < KT) { loadA(nxt, pf * BK2); loadB(nxt, pf * BK2); }
        asm volatile("cp.async.commit_group;\n");

        const unsigned* Ast = As + cur * A_TILE_U32;
        const unsigned* Bst = Bs + cur * BH_TILE;

#pragma unroll
        for (int kt = 0; kt < 2; kt++) {           // two k16 steps per BK2=32
            unsigned af[4][4], bf[4][2];
#pragma unroll
            for (int tm = 0; tm < 4; tm++) {
                int m = wm + tm * 16 + lr;
                // fragment register r holds bf16 pair (k, k+1), k = kt*16+2*lq (+8)
                float2 a0 = *(const float2*)&Ast[m * ASTR3 + kt*16 + 2*lq];
                float2 a1 = *(const float2*)&Ast[(m + 8) * ASTR3 + kt*16 + 2*lq];
                float2 a2 = *(const float2*)&Ast[m * ASTR3 + kt*16 + 2*lq + 8];
                float2 a3 = *(const float2*)&Ast[(m + 8) * ASTR3 + kt*16 + 2*lq + 8];
                af[tm][0] = pack_bf2(a0.x, a0.y);
                af[tm][1] = pack_bf2(a1.x, a1.y);
                af[tm][2] = pack_bf2(a2.x, a2.y);
                af[tm][3] = pack_bf2(a3.x, a3.y);
            }
#pragma unroll
            for (int tn = 0; tn < 4; tn++) {
                int n = wn + tn * 8 + lr;
                bf[tn][0] = Bst[(kt * 8 + lq) * BSTR + n];
                bf[tn][1] = Bst[(kt * 8 + lq + 4) * BSTR + n];
            }
#pragma unroll
            for (int tm = 0; tm < 4; tm++)
#pragma unroll
                for (int tn = 0; tn < 4; tn++)
                    mma_bf16(acc[tm][tn], af[tm], bf[tn][0], bf[tn][1]);
        }
        cur = (cur == 2) ? 0 : cur + 1;
        nxt = (nxt == 2) ? 0 : nxt + 1;
    }

    // epilogue: write bf16 pairs directly
#pragma unroll
    for (int tm = 0; tm < 4; tm++) {
#pragma unroll
        for (int half = 0; half < 2; half++) {
            int row = m0 + wm + tm * 16 + lr + half * 8;
            if (row >= M) continue;
#pragma unroll
            for (int tn = 0; tn < 4; tn++) {
                int col = n0 + wn + tn * 8 + 2 * lq;
                unsigned pr = pack_bf2(acc[tm][tn][half * 2 + 0],
                                       acc[tm][tn][half * 2 + 1]);
                *(unsigned*)&C[(size_t)row * ldc + col] = pr;
            }
        }
    }
}

// ---------------- tensor-core chunked attention (round-15 validated) ---------
#define ATHR 416
#define NW   13
#define KSW 36
#define VS2 212
#define TSW 36
#define ESTR 220
#define ATTN_SMEM ((200*KSW + 64*VS2 + 399*TSW) * 4 + NW*16*ESTR*2)  // 232048 B

__global__ void __launch_bounds__(ATHR, 1)
attn_mma(const unsigned* __restrict__ QKh,   // bf16-pair words, [row][512]
         const float* __restrict__ V,        // [row][512] tf32 values
         const unsigned* __restrict__ Th,    // [399][32] bf16-pair words
         float* __restrict__ AO)
{
    extern __shared__ unsigned smu[];
    unsigned* ksm   = smu;
    unsigned* vsm   = ksm + 200 * KSW;
    unsigned* tsm32 = vsm + 64 * VS2;
    unsigned short* esm = (unsigned short*)(tsm32 + 399 * TSW);

    const int b   = blockIdx.y;
    const int m   = blockIdx.x / HEADS;
    const int h   = blockIdx.x % HEADS;
    const int t0  = m * CTX;
    const int cv  = (NTOK - t0 < CTX) ? (NTOK - t0) : CTX;
    const int tid = threadIdx.x;
    const int w   = tid >> 5, lane = tid & 31;
    const int lr  = lane >> 2, lq = lane & 3;

    for (int idx = tid; idx < 200 * 16; idx += ATHR) {
        int i = idx >> 4, jw2 = (idx & 15) * 2;
        uint2 v = make_uint2(0u, 0u);
        if (i < cv)
            v = *(const uint2*)&QKh[(size_t)(b*NTOK + t0 + i)*512 + 256 + h*32 + jw2];
        *(uint2*)&ksm[i*KSW + jw2] = v;
    }
    for (int idx = tid; idx < 200 * 16; idx += ATHR) {
        int j = idx >> 4, d4 = (idx & 15) * 4;
        if (j < cv) {
            float4 v = *(const float4*)&V[(size_t)(b*NTOK + t0 + j)*512 + h*DH + d4];
            vsm[(d4 + 0)*VS2 + j] = f2tf(v.x);
            vsm[(d4 + 1)*VS2 + j] = f2tf(v.y);
            vsm[(d4 + 2)*VS2 + j] = f2tf(v.z);
            vsm[(d4 + 3)*VS2 + j] = f2tf(v.w);
        } else {
            vsm[(d4 + 0)*VS2 + j] = 0u;
            vsm[(d4 + 1)*VS2 + j] = 0u;
            vsm[(d4 + 2)*VS2 + j] = 0u;
            vsm[(d4 + 3)*VS2 + j] = 0u;
        }
    }
    for (int idx = tid; idx < 399 * 16; idx += ATHR) {
        int r = idx >> 4, c2 = (idx & 15) * 2;
        *(uint2*)&tsm32[r*TSW + c2] = *(const uint2*)&Th[r*32 + c2];
    }
    __syncthreads();

    unsigned short* E0 = esm + w * 16 * ESTR;

    for (int it = w; it * 16 < cv; it += NW) {
        const int i0 = it * 16;
        const int r0 = i0 + lr, r1 = r0 + 8;
        const bool v0 = r0 < cv, v1 = r1 < cv;
        unsigned short* Ea = E0 + lr * ESTR;
        unsigned short* Eb = E0 + (lr + 8) * ESTR;

        unsigned aq[4][4];
        {
            const unsigned* q0 = &QKh[(size_t)(b*NTOK + t0 + r0)*512 + h*32];
            const unsigned* q1 = &QKh[(size_t)(b*NTOK + t0 + r1)*512 + h*32];
#pragma unroll
            for (int kt = 0; kt < 4; kt++) {
                aq[kt][0] = v0 ? q0[kt*8 + lq]     : 0u;
                aq[kt][1] = v1 ? q1[kt*8 + lq]     : 0u;
                aq[kt][2] = v0 ? q0[kt*8 + lq + 4] : 0u;
                aq[kt][3] = v1 ? q1[kt*8 + lq + 4] : 0u;
            }
        }

#pragma unroll 3
        for (int rt = 0; rt < 27; rt++) {
            float ec[4] = {0.f, 0.f, 0.f, 0.f};
            int rg = i0 + rt * 8 + lr;
            bool tv = rg <= 398;
            const unsigned* trow = tsm32 + rg * TSW + lq;
#pragma unroll
            for (int kt = 0; kt < 4; kt++) {
                unsigned b0 = tv ? trow[kt*8]     : 0u;
                unsigned b1 = tv ? trow[kt*8 + 4] : 0u;
                mma_bf16(ec, aq[kt], b0, b1);
            }
            int c0 = rt * 8 + 2 * lq;
            *(unsigned*)&Ea[c0] = pack_bf2(ec[0], ec[1]);
            *(unsigned*)&Eb[c0] = pack_bf2(ec[2], ec[3]);
        }
        __syncwarp();

        float s[25][4];
#pragma unroll
        for (int nt = 0; nt < 25; nt++)
            s[nt][0] = s[nt][1] = s[nt][2] = s[nt][3] = 0.f;
#pragma unroll
        for (int kt = 0; kt < 4; kt++) {
#pragma unroll
            for (int nt = 0; nt < 25; nt++) {
                const unsigned* kr = ksm + (nt*8 + lr)*KSW + kt*8 + lq;
                mma_bf16(s[nt], aq[kt], kr[0], kr[4]);
            }
        }

        float mx0 = -1e30f, mx1 = -1e30f;
#pragma unroll
        for (int nt = 0; nt < 25; nt++) {
            int j0 = nt * 8 + 2 * lq;
#pragma unroll
            for (int e = 0; e < 2; e++) {
                int j = j0 + e;
                float b0f = __uint_as_float((unsigned)Ea[lr     + 199 - j] << 16);
                float b1f = __uint_as_float((unsigned)Eb[lr + 8 + 199 - j] << 16);
                float a0 = s[nt][e]     + b0f;
                float a1 = s[nt][2 + e] + b1f;
                if (j >= cv) { a0 = -1e30f; a1 = -1e30f; }
                s[nt][e] = a0; s[nt][2 + e] = a1;
                mx0 = fmaxf(mx0, a0); mx1 = fmaxf(mx1, a1);
            }
        }
        mx0 = fmaxf(mx0, __shfl_xor_sync(~0u, mx0, 1));
        mx0 = fmaxf(mx0, __shfl_xor_sync(~0u, mx0, 2));
        mx1 = fmaxf(mx1, __shfl_xor_sync(~0u, mx1, 1));
        mx1 = fmaxf(mx1, __shfl_xor_sync(~0u, mx1, 2));

        float sum0 = 0.f, sum1 = 0.f;
#pragma unroll
        for (int nt = 0; nt < 25; nt++) {
#pragma unroll
            for (int e = 0; e < 2; e++) {
                float p0 = __expf(s[nt][e]     - mx0);
                float p1 = __expf(s[nt][2 + e] - mx1);
                s[nt][e] = p0; s[nt][2 + e] = p1;
                sum0 += p0; sum1 += p1;
            }
        }
        sum0 += __shfl_xor_sync(~0u, sum0, 1);
        sum0 += __shfl_xor_sync(~0u, sum0, 2);
        sum1 += __shfl_xor_sync(~0u, sum1, 1);
        sum1 += __shfl_xor_sync(~0u, sum1, 2);
        const float inv0 = 1.f / sum0, inv1 = 1.f / sum1;

        float o[8][4];
#pragma unroll
        for (int nt = 0; nt < 8; nt++)
            o[nt][0] = o[nt][1] = o[nt][2] = o[nt][3] = 0.f;

        const int src1 = (lane & ~3) | (lq >> 1);
        const int src2 = src1 + 2;
        const bool odd = lq & 1;
#pragma unroll
        for (int kt = 0; kt < 25; kt++) {
            float x0 = __shfl_sync(~0u, s[kt][0], src1);
            float x1 = __shfl_sync(~0u, s[kt][1], src1);
            float y0 = __shfl_sync(~0u, s[kt][2], src1);
            float y1 = __shfl_sync(~0u, s[kt][3], src1);
            float z0 = __shfl_sync(~0u, s[kt][0], src2);
            float z1 = __shfl_sync(~0u, s[kt][1], src2);
            float u0 = __shfl_sync(~0u, s[kt][2], src2);
            float u1 = __shfl_sync(~0u, s[kt][3], src2);
            unsigned pa[4];
            pa[0] = f2tf(odd ? x1 : x0);
            pa[1] = f2tf(odd ? y1 : y0);
            pa[2] = f2tf(odd ? z1 : z0);
            pa[3] = f2tf(odd ? u1 : u0);
#pragma unroll
            for (int nt = 0; nt < 8; nt++) {
                unsigned b0 = vsm[(nt*8 + lr)*VS2 + kt*8 + lq];
                unsigned b1 = vsm[(nt*8 + lr)*VS2 + kt*8 + lq + 4];
                mma_tf32(o[nt], pa, b0, b1);
            }
        }

#pragma unroll
        for (int nt = 0; nt < 8; nt++) {
            int col = h*DH + nt*8 + 2*lq;
            if (v0) {
                float2 t2 = make_float2(f2tf_f(o[nt][0]*inv0), f2tf_f(o[nt][1]*inv0));
                *(float2*)&AO[(size_t)(b*NTOK + t0 + r0)*DIM + col] = t2;
            }
            if (v1) {
                float2 t2 = make_float2(f2tf_f(o[nt][2]*inv1), f2tf_f(o[nt][3]*inv1));
                *(float2*)&AO[(size_t)(b*NTOK + t0 + r1)*DIM + col] = t2;
            }
        }
        __syncwarp();
    }
}

// ---------------- launcher ----------------
extern "C" void kernel_launch(void* const* d_in, const int* in_sizes, int n_in,
                              void* d_out, int out_size)
{
    const float* x      = (const float*)d_in[0];
    const float* wq     = (const float*)d_in[1];
    const float* wkv    = (const float*)d_in[2];
    const float* wout_w = (const float*)d_in[3];
    const float* wout_b = (const float*)d_in[4];
    const float* rel    = (const float*)d_in[5];
    float* out = (float*)d_out;

    void *pqkh, *pv, *pao, *pwqk, *pth;
    cudaGetSymbolAddress(&pqkh, g_qkh);
    cudaGetSymbolAddress(&pv,   g_v);
    cudaGetSymbolAddress(&pao,  g_ao);
    cudaGetSymbolAddress(&pwqk, g_wqkh);
    cudaGetSymbolAddress(&pth,  g_th);

    cudaFuncSetAttribute(attn_mma,
                         cudaFuncAttributeMaxDynamicSharedMemorySize, ATTN_SMEM);
    cudaFuncSetAttribute(gemm_tf32<false, true, true>,
                         cudaFuncAttributeMaxDynamicSharedMemorySize, GEMM_SMEM);
    cudaFuncSetAttribute(gemm_tf32<true, false, true>,
                         cudaFuncAttributeMaxDynamicSharedMemorySize, GEMM_SMEM);
    cudaFuncSetAttribute(gemm_bf16,
                         cudaFuncAttributeMaxDynamicSharedMemorySize, GEMMH_SMEM);

    const int M = MROWS;
    dim3 blk(256);

    pack_wqk<<<((DIM/2) * 1024 + 255) / 256, 256>>>(wq, wkv, (unsigned*)pwqk);
    pack_t<<<(399 * 32 + 255) / 256, 256>>>(rel, (unsigned*)pth);

    // [0.125*Q | K] = X @ Wqk (raw fp32 A, bf16 MMA, bf16 out)
    dim3 gqk(1024 / BN, (M + BM - 1) / BM);
    gemm_bf16<<<gqk, blk, GEMMH_SMEM>>>(x, (const unsigned*)pwqk,
                                        (__nv_bfloat16*)pqkh, M, 1024, DIM, 1024);

    // V = X @ Wkv[:,512:] (tf32; A and B rounded in-register, ldb=1024)
    dim3 gv(DIM / BN, (M + BM - 1) / BM);
    gemm_tf32<false, true, true><<<gv, blk, GEMM_SMEM>>>(
        x, wkv + DIM, nullptr, (float*)pv, M, DIM, DIM, 1024, DIM);

    attn_mma<<<dim3(NB * HEADS, BS), dim3(ATHR), ATTN_SMEM>>>(
        (const unsigned*)pqkh, (const float*)pv, (const unsigned*)pth,
        (float*)pao);

    // out = AO @ Wout + b (tf32; B rounded in-register)
    dim3 gout(DIM / BN, (M + BM - 1) / BM);
    gemm_tf32<true, false, true><<<gout, blk, GEMM_SMEM>>>(
        (const float*)pao, wout_w, wout_b, out, M, DIM, DIM, DIM, DIM);
}